// round 2
// baseline (speedup 1.0000x reference)
#include <cuda_runtime.h>
#include <math.h>

// ---------------- problem constants ----------------
#define BATCH   32
#define NCLS    60
#define BNC     1920          // BATCH*NCLS
#define DD      256
#define SS      72
#define NH      8
#define HDIM    32
#define TOPM    20
#define NLAYERS 2
#define MTOT    (BNC*SS)      // 138240 rows
#define LN_EPS  1e-5f

// ---------------- scratch (device globals; no cudaMalloc allowed) ----------------
__device__ float g_x  [(size_t)MTOT*DD];      // current activations (B,S,D)
__device__ float g_qkv[(size_t)MTOT*3*DD];    // qkv projections
__device__ float g_att[(size_t)MTOT*DD];      // attention output
__device__ float g_tmp[(size_t)MTOT*DD];      // proj + residual (pre-LN)
__device__ float g_mean[BNC*DD];              // seq-mean features

// ---------------- kernel 1: transpose (BNC,D,S)->(BNC,S,D) + pos embed ----------------
__global__ __launch_bounds__(256) void k_transpose(const float* __restrict__ f,
                                                   const float* __restrict__ pos,
                                                   float* __restrict__ x) {
    __shared__ float t[32][33];
    int b  = blockIdx.x;
    int s0 = blockIdx.y * 32;
    int d0 = blockIdx.z * 32;
    int tx = threadIdx.x, ty = threadIdx.y;       // block (32,8)
    const float* fb = f + (size_t)b * DD * SS;
    #pragma unroll
    for (int i = 0; i < 4; i++) {
        int d = d0 + ty + i*8;
        int s = s0 + tx;
        t[ty + i*8][tx] = (s < SS) ? fb[d * SS + s] : 0.f;
    }
    __syncthreads();
    float* xb = x + (size_t)b * SS * DD;
    #pragma unroll
    for (int i = 0; i < 4; i++) {
        int s = s0 + ty + i*8;
        int d = d0 + tx;
        if (s < SS) xb[s * DD + d] = t[tx][ty + i*8] + pos[s * DD + d];
    }
}

// ---------------- kernel 2: SGEMM  C[M,N] = A[M,256] @ B[256,N] + bias (+res) ----------------
// 64x64 block tile, K-chunk 32, 256 threads, 4x4 per thread. M,N multiples of 64.
__global__ __launch_bounds__(256) void k_gemm(const float* __restrict__ A,
                                              const float* __restrict__ B,
                                              const float* __restrict__ bias,
                                              const float* __restrict__ res,
                                              float* __restrict__ C, int N) {
    __shared__ __align__(16) float As[32][68];   // [k][m]
    __shared__ __align__(16) float Bs[32][68];   // [k][n]
    const int tid = threadIdx.x;
    const int m0 = blockIdx.y * 64, n0 = blockIdx.x * 64;
    const int tm = tid >> 4, tn = tid & 15;
    float acc[4][4] = {};
    for (int k0 = 0; k0 < 256; k0 += 32) {
        #pragma unroll
        for (int i = 0; i < 2; i++) {            // A tile 64x32 (512 float4)
            int li = tid * 2 + i;
            int m  = li >> 3;
            int kc = li & 7;
            float4 v = *(const float4*)(A + (size_t)(m0 + m) * 256 + k0 + kc * 4);
            As[kc*4+0][m] = v.x; As[kc*4+1][m] = v.y;
            As[kc*4+2][m] = v.z; As[kc*4+3][m] = v.w;
        }
        #pragma unroll
        for (int i = 0; i < 2; i++) {            // B tile 32x64
            int li = tid * 2 + i;
            int kr = li >> 4;
            int nc = li & 15;
            *(float4*)&Bs[kr][nc*4] =
                *(const float4*)(B + (size_t)(k0 + kr) * N + n0 + nc * 4);
        }
        __syncthreads();
        #pragma unroll
        for (int kk = 0; kk < 32; kk++) {
            float4 a  = *(const float4*)&As[kk][tm*4];
            float4 bv = *(const float4*)&Bs[kk][tn*4];
            float av[4] = {a.x, a.y, a.z, a.w};
            float bw[4] = {bv.x, bv.y, bv.z, bv.w};
            #pragma unroll
            for (int i = 0; i < 4; i++)
                #pragma unroll
                for (int j = 0; j < 4; j++)
                    acc[i][j] += av[i] * bw[j];
        }
        __syncthreads();
    }
    float4 bb = *(const float4*)(bias + n0 + tn * 4);
    #pragma unroll
    for (int i = 0; i < 4; i++) {
        int m = m0 + tm * 4 + i;
        float4 o;
        o.x = acc[i][0] + bb.x; o.y = acc[i][1] + bb.y;
        o.z = acc[i][2] + bb.z; o.w = acc[i][3] + bb.w;
        if (res) {
            float4 r = *(const float4*)(res + (size_t)m * N + n0 + tn * 4);
            o.x += r.x; o.y += r.y; o.z += r.z; o.w += r.w;
        }
        *(float4*)(C + (size_t)m * N + n0 + tn * 4) = o;
    }
}

// ---------------- kernel 3: top-M attention per (batch, head) ----------------
__global__ __launch_bounds__(256) void k_attn(const float* __restrict__ qkv,
                                              float* __restrict__ out) {
    __shared__ float sq[SS][33];   // q, later reused for v
    __shared__ float sk[SS][33];
    __shared__ float sc[SS][73];   // scores -> probs
    const int b = blockIdx.x;
    const int h = blockIdx.y;
    const int tid = threadIdx.x;
    const float* base = qkv + (size_t)b * SS * 768 + h * HDIM;
    // load q, k
    for (int idx = tid; idx < SS * HDIM; idx += 256) {
        int s_ = idx >> 5, d = idx & 31;
        sq[s_][d] = base[s_ * 768 +       d];
        sk[s_][d] = base[s_ * 768 + 256 + d];
    }
    __syncthreads();
    // scores = q @ k^T * scale   (72x72x32) — 16x16 threads, 5x5 each
    const int ty = tid >> 4, tx = tid & 15;
    {
        const float scale = 0.17677669529663687f;   // 32^-0.5
        float a[5], bb[5], acc[5][5] = {};
        int r0 = ty * 5, c0 = tx * 5;
        for (int kk = 0; kk < HDIM; kk++) {
            #pragma unroll
            for (int i = 0; i < 5; i++) a[i]  = sq[min(r0 + i, SS-1)][kk];
            #pragma unroll
            for (int j = 0; j < 5; j++) bb[j] = sk[min(c0 + j, SS-1)][kk];
            #pragma unroll
            for (int i = 0; i < 5; i++)
                #pragma unroll
                for (int j = 0; j < 5; j++)
                    acc[i][j] += a[i] * bb[j];
        }
        #pragma unroll
        for (int i = 0; i < 5; i++)
            #pragma unroll
            for (int j = 0; j < 5; j++) {
                int r = r0 + i, c = c0 + j;
                if (r < SS && c < SS) sc[r][c] = acc[i][j] * scale;
            }
    }
    __syncthreads();
    // reuse sq for v
    for (int idx = tid; idx < SS * HDIM; idx += 256) {
        int s_ = idx >> 5, d = idx & 31;
        sq[s_][d] = base[s_ * 768 + 512 + d];
    }
    // top-20 threshold + softmax, one thread per row
    if (tid < SS) {
        float top[TOPM];
        #pragma unroll
        for (int i = 0; i < TOPM; i++) top[i] = -INFINITY;
        for (int c = 0; c < SS; c++) {
            float val = sc[tid][c];
            if (val > top[TOPM-1]) {
                int p = TOPM - 1;
                while (p > 0 && top[p-1] < val) { top[p] = top[p-1]; p--; }
                top[p] = val;
            }
        }
        float thr = top[TOPM-1], mx = top[0];
        float sum = 0.f;
        for (int c = 0; c < SS; c++) {
            float v = sc[tid][c];
            float e = (v >= thr) ? __expf(v - mx) : 0.f;
            sc[tid][c] = e;
            sum += e;
        }
        float inv = 1.f / sum;
        for (int c = 0; c < SS; c++) sc[tid][c] *= inv;
    }
    __syncthreads();
    // out = p @ v  (72x32x72) — 16x16 threads, 5 rows x 2 cols each
    {
        int r0 = ty * 5, c0 = tx * 2;
        float acc[5][2] = {};
        for (int kk = 0; kk < SS; kk++) {
            float v0 = sq[kk][c0], v1 = sq[kk][c0 + 1];
            #pragma unroll
            for (int i = 0; i < 5; i++) {
                float p = sc[min(r0 + i, SS-1)][kk];
                acc[i][0] += p * v0;
                acc[i][1] += p * v1;
            }
        }
        #pragma unroll
        for (int i = 0; i < 5; i++) {
            int r = r0 + i;
            if (r < SS) {
                float* o = out + (size_t)(b * SS + r) * DD + h * HDIM + c0;
                o[0] = acc[i][0];
                o[1] = acc[i][1];
            }
        }
    }
}

// ---------------- kernel 4: LayerNorm over D=256 ----------------
__global__ __launch_bounds__(256) void k_ln(const float* __restrict__ y,
                                            const float* __restrict__ g,
                                            const float* __restrict__ bt,
                                            float* __restrict__ x) {
    __shared__ float sh[8];
    const int row = blockIdx.x;
    const int tid = threadIdx.x;
    const int lane = tid & 31, wid = tid >> 5;
    float v = y[(size_t)row * DD + tid];
    // mean
    float s = v;
    #pragma unroll
    for (int o = 16; o > 0; o >>= 1) s += __shfl_xor_sync(0xffffffffu, s, o);
    if (lane == 0) sh[wid] = s;
    __syncthreads();
    float mu;
    {
        float t = (tid < 8) ? sh[tid] : 0.f;
        if (wid == 0) {
            #pragma unroll
            for (int o = 4; o > 0; o >>= 1) t += __shfl_xor_sync(0xffffffffu, t, o);
            if (lane == 0) sh[0] = t * (1.f / DD);
        }
    }
    __syncthreads();
    mu = sh[0];
    __syncthreads();
    // variance
    float d = v - mu;
    float s2 = d * d;
    #pragma unroll
    for (int o = 16; o > 0; o >>= 1) s2 += __shfl_xor_sync(0xffffffffu, s2, o);
    if (lane == 0) sh[wid] = s2;
    __syncthreads();
    if (wid == 0) {
        float t = (tid < 8) ? sh[tid] : 0.f;
        #pragma unroll
        for (int o = 4; o > 0; o >>= 1) t += __shfl_xor_sync(0xffffffffu, t, o);
        if (lane == 0) sh[0] = rsqrtf(t * (1.f / DD) + LN_EPS);
    }
    __syncthreads();
    float rstd = sh[0];
    x[(size_t)row * DD + tid] = d * rstd * g[tid] + bt[tid];
}

// ---------------- kernel 5: mean over sequence ----------------
__global__ __launch_bounds__(256) void k_mean(const float* __restrict__ x,
                                              float* __restrict__ m) {
    const int b = blockIdx.x;
    const int tid = threadIdx.x;
    float acc = 0.f;
    #pragma unroll 8
    for (int s = 0; s < SS; s++)
        acc += x[(size_t)(b * SS + s) * DD + tid];
    m[b * DD + tid] = acc * (1.f / SS);
}

// ---------------- kernel 6: classifier MLP ----------------
__global__ __launch_bounds__(128) void k_cls(const float* __restrict__ m,
                                             const float* __restrict__ w1,
                                             const float* __restrict__ b1,
                                             const float* __restrict__ w2,
                                             const float* __restrict__ b2,
                                             float* __restrict__ out) {
    __shared__ float xm[DD];
    __shared__ float sh[4];
    const int b = blockIdx.x;
    const int tid = threadIdx.x;          // 128
    xm[tid]       = m[b * DD + tid];
    xm[tid + 128] = m[b * DD + tid + 128];
    __syncthreads();
    float acc = b1[tid];
    #pragma unroll 8
    for (int k = 0; k < DD; k++)
        acc += xm[k] * w1[k * 128 + tid];
    float contrib = fmaxf(acc, 0.f) * w2[tid];
    const int lane = tid & 31, wid = tid >> 5;
    #pragma unroll
    for (int o = 16; o > 0; o >>= 1) contrib += __shfl_xor_sync(0xffffffffu, contrib, o);
    if (lane == 0) sh[wid] = contrib;
    __syncthreads();
    if (tid == 0)
        out[b] = sh[0] + sh[1] + sh[2] + sh[3] + b2[0];
}

// ---------------- launch ----------------
extern "C" void kernel_launch(void* const* d_in, const int* in_sizes, int n_in,
                              void* d_out, int out_size) {
    const float* feats  = (const float*)d_in[0];   // (1920,256,72)
    const float* pos    = (const float*)d_in[1];   // (1,72,256)
    const float* qkv_w  = (const float*)d_in[2];   // (2,256,768)
    const float* qkv_b  = (const float*)d_in[3];   // (2,768)
    const float* proj_w = (const float*)d_in[4];   // (2,256,256)
    const float* proj_b = (const float*)d_in[5];   // (2,256)
    const float* ln_g   = (const float*)d_in[6];   // (2,256)
    const float* ln_b   = (const float*)d_in[7];   // (2,256)
    const float* cls_w1 = (const float*)d_in[8];   // (256,128)
    const float* cls_b1 = (const float*)d_in[9];   // (128)
    const float* cls_w2 = (const float*)d_in[10];  // (128,1)
    const float* cls_b2 = (const float*)d_in[11];  // (1)
    float* out = (float*)d_out;                    // (32,60) -> 1920

    float *px, *pqkv, *patt, *ptmp, *pmean;
    cudaGetSymbolAddress((void**)&px,    g_x);
    cudaGetSymbolAddress((void**)&pqkv,  g_qkv);
    cudaGetSymbolAddress((void**)&patt,  g_att);
    cudaGetSymbolAddress((void**)&ptmp,  g_tmp);
    cudaGetSymbolAddress((void**)&pmean, g_mean);

    // 1) x = transpose(features) + pos
    {
        dim3 grid(BNC, 3, 8), blk(32, 8);
        k_transpose<<<grid, blk>>>(feats, pos, px);
    }
    // 2) transformer layers
    for (int l = 0; l < NLAYERS; l++) {
        const float* qw = qkv_w  + (size_t)l * 256 * 768;
        const float* qb = qkv_b  + (size_t)l * 768;
        const float* pw = proj_w + (size_t)l * 256 * 256;
        const float* pb = proj_b + (size_t)l * 256;
        const float* lg = ln_g   + (size_t)l * 256;
        const float* lb = ln_b   + (size_t)l * 256;

        {   // qkv = x @ qw + qb
            dim3 grid(768 / 64, MTOT / 64);
            k_gemm<<<grid, 256>>>(px, qw, qb, nullptr, pqkv, 768);
        }
        {   // attention
            dim3 grid(BNC, NH);
            k_attn<<<grid, 256>>>(pqkv, patt);
        }
        {   // tmp = att @ pw + pb + x  (residual)
            dim3 grid(256 / 64, MTOT / 64);
            k_gemm<<<grid, 256>>>(patt, pw, pb, px, ptmp, 256);
        }
        // x = LN(tmp)
        k_ln<<<MTOT, 256>>>(ptmp, lg, lb, px);
    }
    // 3) mean over sequence
    k_mean<<<BNC, 256>>>(px, pmean);
    // 4) classifier
    k_cls<<<BNC, 128>>>(pmean, cls_w1, cls_b1, cls_w2, cls_b2, out);
}

// round 4
// speedup vs baseline: 2.5768x; 2.5768x over previous
#include <cuda_runtime.h>
#include <math.h>

// ---------------- problem constants ----------------
#define BATCH   32
#define NCLS    60
#define BNC     1920          // BATCH*NCLS
#define DD      256
#define SS      72
#define NH      8
#define HDIM    32
#define TOPM    20
#define NLAYERS 2
#define MTOT    (BNC*SS)      // 138240 rows
#define LN_EPS  1e-5f

// ---------------- scratch (device globals; no cudaMalloc allowed) ----------------
__device__ float g_x  [(size_t)MTOT*DD];      // current activations (B,S,D)
__device__ float g_qkv[(size_t)MTOT*3*DD];    // qkv projections
__device__ float g_att[(size_t)MTOT*DD];      // attention output
__device__ float g_tmp[(size_t)MTOT*DD];      // proj + residual (pre-LN)
__device__ float g_mean[BNC*DD];              // seq-mean features

// ---------------- tf32 helpers ----------------
__device__ __forceinline__ unsigned f2tf32(float f) {
    unsigned r;
    asm("cvt.rna.tf32.f32 %0, %1;" : "=r"(r) : "f"(f));
    return r;
}

__device__ __forceinline__ void mma_tf32(float* c, const unsigned* a, const unsigned* b) {
    asm volatile(
        "mma.sync.aligned.m16n8k8.row.col.f32.tf32.tf32.f32 "
        "{%0,%1,%2,%3}, {%4,%5,%6,%7}, {%8,%9}, {%0,%1,%2,%3};"
        : "+f"(c[0]), "+f"(c[1]), "+f"(c[2]), "+f"(c[3])
        : "r"(a[0]), "r"(a[1]), "r"(a[2]), "r"(a[3]),
          "r"(b[0]), "r"(b[1]));
}

// ---------------- kernel 1: transpose (BNC,D,S)->(BNC,S,D) + pos embed ----------------
__global__ __launch_bounds__(256) void k_transpose(const float* __restrict__ f,
                                                   const float* __restrict__ pos,
                                                   float* __restrict__ x) {
    __shared__ float t[32][33];
    int b  = blockIdx.x;
    int s0 = blockIdx.y * 32;
    int d0 = blockIdx.z * 32;
    int tx = threadIdx.x, ty = threadIdx.y;       // block (32,8)
    const float* fb = f + (size_t)b * DD * SS;
    #pragma unroll
    for (int i = 0; i < 4; i++) {
        int d = d0 + ty + i*8;
        int s = s0 + tx;
        t[ty + i*8][tx] = (s < SS) ? fb[d * SS + s] : 0.f;
    }
    __syncthreads();
    float* xb = x + (size_t)b * SS * DD;
    #pragma unroll
    for (int i = 0; i < 4; i++) {
        int s = s0 + ty + i*8;
        int d = d0 + tx;
        if (s < SS) xb[s * DD + d] = t[tx][ty + i*8] + pos[s * DD + d];
    }
}

// ---------------- kernel 2: tf32 tensor-core GEMM ----------------
// C[M,N] = A[M,256] @ B[256,N] + bias (+res).  Block tile 128x64, 8 warps (4m x 2n),
// each warp 32x32 via m16n8k8 tf32 mma (2 m-tiles x 4 n-tiles). K chunked by 32.
// SMEM bank-conflict-free: As stride 36 (banks 4g+t), Bs stride 72 (banks 8t+g).
__global__ __launch_bounds__(256) void k_gemm_tf32(const float* __restrict__ A,
                                                   const float* __restrict__ B,
                                                   const float* __restrict__ bias,
                                                   const float* __restrict__ res,
                                                   float* __restrict__ C, int N) {
    __shared__ __align__(16) unsigned As[128][36];
    __shared__ __align__(16) unsigned Bs[32][72];
    const int tid  = threadIdx.x;
    const int m0   = blockIdx.y * 128;
    const int n0   = blockIdx.x * 64;
    const int warp = tid >> 5, lane = tid & 31;
    const int wm   = warp & 3;    // 0..3 -> m offset 32*wm
    const int wn   = warp >> 2;   // 0..1 -> n offset 32*wn
    const int g    = lane >> 2;   // group id 0..7
    const int t    = lane & 3;    // thread in group 0..3

    float acc[2][4][4];
    #pragma unroll
    for (int i = 0; i < 2; i++)
        #pragma unroll
        for (int j = 0; j < 4; j++)
            #pragma unroll
            for (int r = 0; r < 4; r++) acc[i][j][r] = 0.f;

    for (int k0 = 0; k0 < 256; k0 += 32) {
        // A tile 128x32 -> 1024 float4, 4 per thread (cvt to tf32 on the way in)
        #pragma unroll
        for (int i = 0; i < 4; i++) {
            int idx = tid + i * 256;
            int m = idx >> 3, kc = idx & 7;
            float4 v = *(const float4*)(A + (size_t)(m0 + m) * 256 + k0 + kc * 4);
            uint4 u;
            u.x = f2tf32(v.x); u.y = f2tf32(v.y);
            u.z = f2tf32(v.z); u.w = f2tf32(v.w);
            *(uint4*)&As[m][kc * 4] = u;
        }
        // B tile 32x64 -> 512 float4, 2 per thread
        #pragma unroll
        for (int i = 0; i < 2; i++) {
            int idx = tid + i * 256;
            int k = idx >> 4, nc = idx & 15;
            float4 v = *(const float4*)(B + (size_t)(k0 + k) * N + n0 + nc * 4);
            uint4 u;
            u.x = f2tf32(v.x); u.y = f2tf32(v.y);
            u.z = f2tf32(v.z); u.w = f2tf32(v.w);
            *(uint4*)&Bs[k][nc * 4] = u;
        }
        __syncthreads();
        #pragma unroll
        for (int ks = 0; ks < 4; ks++) {
            unsigned a[2][4], b[4][2];
            #pragma unroll
            for (int mt = 0; mt < 2; mt++) {
                int mr = wm * 32 + mt * 16;
                a[mt][0] = As[mr + g    ][ks * 8 + t    ];
                a[mt][1] = As[mr + g + 8][ks * 8 + t    ];
                a[mt][2] = As[mr + g    ][ks * 8 + t + 4];
                a[mt][3] = As[mr + g + 8][ks * 8 + t + 4];
            }
            #pragma unroll
            for (int nt = 0; nt < 4; nt++) {
                int nc = wn * 32 + nt * 8;
                b[nt][0] = Bs[ks * 8 + t    ][nc + g];
                b[nt][1] = Bs[ks * 8 + t + 4][nc + g];
            }
            #pragma unroll
            for (int mt = 0; mt < 2; mt++)
                #pragma unroll
                for (int nt = 0; nt < 4; nt++)
                    mma_tf32(acc[mt][nt], a[mt], b[nt]);
        }
        __syncthreads();
    }
    // epilogue: bias (+residual), float2 stores
    #pragma unroll
    for (int mt = 0; mt < 2; mt++) {
        #pragma unroll
        for (int nt = 0; nt < 4; nt++) {
            int m = m0 + wm * 32 + mt * 16 + g;
            int n = n0 + wn * 32 + nt * 8 + 2 * t;
            float bx = bias[n], by = bias[n + 1];
            float2 o0 = make_float2(acc[mt][nt][0] + bx, acc[mt][nt][1] + by);
            float2 o1 = make_float2(acc[mt][nt][2] + bx, acc[mt][nt][3] + by);
            if (res) {
                float2 r0 = *(const float2*)(res + (size_t)m * N + n);
                float2 r1 = *(const float2*)(res + (size_t)(m + 8) * N + n);
                o0.x += r0.x; o0.y += r0.y;
                o1.x += r1.x; o1.y += r1.y;
            }
            *(float2*)(C + (size_t)m * N + n)       = o0;
            *(float2*)(C + (size_t)(m + 8) * N + n) = o1;
        }
    }
}

// ---------------- kernel 3: top-M attention per (batch, head) ----------------
__global__ __launch_bounds__(256) void k_attn(const float* __restrict__ qkv,
                                              float* __restrict__ out) {
    __shared__ float sq[SS][33];   // q, later reused for v
    __shared__ float sk[SS][33];
    __shared__ float sc[SS][73];   // scores -> probs
    const int b = blockIdx.x;
    const int h = blockIdx.y;
    const int tid = threadIdx.x;
    const float* base = qkv + (size_t)b * SS * 768 + h * HDIM;
    // load q, k
    for (int idx = tid; idx < SS * HDIM; idx += 256) {
        int s_ = idx >> 5, d = idx & 31;
        sq[s_][d] = base[s_ * 768 +       d];
        sk[s_][d] = base[s_ * 768 + 256 + d];
    }
    __syncthreads();
    // scores = q @ k^T * scale   (72x72x32) — 16x16 threads, 5x5 each
    const int ty = tid >> 4, tx = tid & 15;
    {
        const float scale = 0.17677669529663687f;   // 32^-0.5
        float a[5], bb[5], accs[5][5] = {};
        int r0 = ty * 5, c0 = tx * 5;
        for (int kk = 0; kk < HDIM; kk++) {
            #pragma unroll
            for (int i = 0; i < 5; i++) a[i]  = sq[min(r0 + i, SS-1)][kk];
            #pragma unroll
            for (int j = 0; j < 5; j++) bb[j] = sk[min(c0 + j, SS-1)][kk];
            #pragma unroll
            for (int i = 0; i < 5; i++)
                #pragma unroll
                for (int j = 0; j < 5; j++)
                    accs[i][j] += a[i] * bb[j];
        }
        #pragma unroll
        for (int i = 0; i < 5; i++)
            #pragma unroll
            for (int j = 0; j < 5; j++) {
                int r = r0 + i, c = c0 + j;
                if (r < SS && c < SS) sc[r][c] = accs[i][j] * scale;
            }
    }
    __syncthreads();
    // reuse sq for v
    for (int idx = tid; idx < SS * HDIM; idx += 256) {
        int s_ = idx >> 5, d = idx & 31;
        sq[s_][d] = base[s_ * 768 + 512 + d];
    }
    // top-20 threshold + softmax, one thread per row.
    // Register-only sorted list via unrolled fmax/fmin swap chain (no dynamic indexing!)
    if (tid < SS) {
        float top[TOPM];
        #pragma unroll
        for (int i = 0; i < TOPM; i++) top[i] = -INFINITY;
        for (int c = 0; c < SS; c++) {
            float val = sc[tid][c];
            if (val > top[TOPM-1]) {
                #pragma unroll
                for (int i = 0; i < TOPM; i++) {
                    float hi = fmaxf(top[i], val);
                    val      = fminf(top[i], val);
                    top[i]   = hi;
                }
            }
        }
        float thr = top[TOPM-1], mx = top[0];
        float sum = 0.f;
        for (int c = 0; c < SS; c++) {
            float v = sc[tid][c];
            float e = (v >= thr) ? __expf(v - mx) : 0.f;
            sc[tid][c] = e;
            sum += e;
        }
        float inv = 1.f / sum;
        for (int c = 0; c < SS; c++) sc[tid][c] *= inv;
    }
    __syncthreads();
    // out = p @ v  (72x32x72) — 16x16 threads, 5 rows x 2 cols each
    {
        int r0 = ty * 5, c0 = tx * 2;
        float accs[5][2] = {};
        for (int kk = 0; kk < SS; kk++) {
            float v0 = sq[kk][c0], v1 = sq[kk][c0 + 1];
            #pragma unroll
            for (int i = 0; i < 5; i++) {
                float p = sc[min(r0 + i, SS-1)][kk];
                accs[i][0] += p * v0;
                accs[i][1] += p * v1;
            }
        }
        #pragma unroll
        for (int i = 0; i < 5; i++) {
            int r = r0 + i;
            if (r < SS) {
                float* o = out + (size_t)(b * SS + r) * DD + h * HDIM + c0;
                o[0] = accs[i][0];
                o[1] = accs[i][1];
            }
        }
    }
}

// ---------------- kernel 4: LayerNorm over D=256, warp per row ----------------
__global__ __launch_bounds__(256) void k_ln(const float* __restrict__ y,
                                            const float* __restrict__ g,
                                            const float* __restrict__ bt,
                                            float* __restrict__ x) {
    const int row  = blockIdx.x * 8 + (threadIdx.x >> 5);
    const int lane = threadIdx.x & 31;
    const float* yr = y + (size_t)row * DD + lane * 8;
    float4 v0 = *(const float4*)(yr);
    float4 v1 = *(const float4*)(yr + 4);
    float s = v0.x + v0.y + v0.z + v0.w + v1.x + v1.y + v1.z + v1.w;
    #pragma unroll
    for (int o = 16; o > 0; o >>= 1) s += __shfl_xor_sync(0xffffffffu, s, o);
    float mu = s * (1.f / DD);
    float d0x = v0.x - mu, d0y = v0.y - mu, d0z = v0.z - mu, d0w = v0.w - mu;
    float d1x = v1.x - mu, d1y = v1.y - mu, d1z = v1.z - mu, d1w = v1.w - mu;
    float s2 = d0x*d0x + d0y*d0y + d0z*d0z + d0w*d0w
             + d1x*d1x + d1y*d1y + d1z*d1z + d1w*d1w;
    #pragma unroll
    for (int o = 16; o > 0; o >>= 1) s2 += __shfl_xor_sync(0xffffffffu, s2, o);
    float rstd = rsqrtf(s2 * (1.f / DD) + LN_EPS);
    float4 g0 = *(const float4*)(g  + lane * 8);
    float4 g1 = *(const float4*)(g  + lane * 8 + 4);
    float4 b0 = *(const float4*)(bt + lane * 8);
    float4 b1 = *(const float4*)(bt + lane * 8 + 4);
    float4 o0, o1;
    o0.x = d0x * rstd * g0.x + b0.x; o0.y = d0y * rstd * g0.y + b0.y;
    o0.z = d0z * rstd * g0.z + b0.z; o0.w = d0w * rstd * g0.w + b0.w;
    o1.x = d1x * rstd * g1.x + b1.x; o1.y = d1y * rstd * g1.y + b1.y;
    o1.z = d1z * rstd * g1.z + b1.z; o1.w = d1w * rstd * g1.w + b1.w;
    float* xr = x + (size_t)row * DD + lane * 8;
    *(float4*)(xr)     = o0;
    *(float4*)(xr + 4) = o1;
}

// ---------------- kernel 5: mean over sequence ----------------
__global__ __launch_bounds__(256) void k_mean(const float* __restrict__ x,
                                              float* __restrict__ m) {
    const int b = blockIdx.x;
    const int tid = threadIdx.x;
    float acc = 0.f;
    #pragma unroll 8
    for (int s = 0; s < SS; s++)
        acc += x[(size_t)(b * SS + s) * DD + tid];
    m[b * DD + tid] = acc * (1.f / SS);
}

// ---------------- kernel 6: classifier MLP ----------------
__global__ __launch_bounds__(128) void k_cls(const float* __restrict__ m,
                                             const float* __restrict__ w1,
                                             const float* __restrict__ b1,
                                             const float* __restrict__ w2,
                                             const float* __restrict__ b2,
                                             float* __restrict__ out) {
    __shared__ float xm[DD];
    __shared__ float sh[4];
    const int b = blockIdx.x;
    const int tid = threadIdx.x;          // 128
    xm[tid]       = m[b * DD + tid];
    xm[tid + 128] = m[b * DD + tid + 128];
    __syncthreads();
    float acc = b1[tid];
    #pragma unroll 8
    for (int k = 0; k < DD; k++)
        acc += xm[k] * w1[k * 128 + tid];
    float contrib = fmaxf(acc, 0.f) * w2[tid];
    const int lane = tid & 31, wid = tid >> 5;
    #pragma unroll
    for (int o = 16; o > 0; o >>= 1) contrib += __shfl_xor_sync(0xffffffffu, contrib, o);
    if (lane == 0) sh[wid] = contrib;
    __syncthreads();
    if (tid == 0)
        out[b] = sh[0] + sh[1] + sh[2] + sh[3] + b2[0];
}

// ---------------- launch ----------------
extern "C" void kernel_launch(void* const* d_in, const int* in_sizes, int n_in,
                              void* d_out, int out_size) {
    const float* feats  = (const float*)d_in[0];   // (1920,256,72)
    const float* pos    = (const float*)d_in[1];   // (1,72,256)
    const float* qkv_w  = (const float*)d_in[2];   // (2,256,768)
    const float* qkv_b  = (const float*)d_in[3];   // (2,768)
    const float* proj_w = (const float*)d_in[4];   // (2,256,256)
    const float* proj_b = (const float*)d_in[5];   // (2,256)
    const float* ln_g   = (const float*)d_in[6];   // (2,256)
    const float* ln_b   = (const float*)d_in[7];   // (2,256)
    const float* cls_w1 = (const float*)d_in[8];   // (256,128)
    const float* cls_b1 = (const float*)d_in[9];   // (128)
    const float* cls_w2 = (const float*)d_in[10];  // (128,1)
    const float* cls_b2 = (const float*)d_in[11];  // (1)
    float* out = (float*)d_out;                    // (32,60) -> 1920

    float *px, *pqkv, *patt, *ptmp, *pmean;
    cudaGetSymbolAddress((void**)&px,    g_x);
    cudaGetSymbolAddress((void**)&pqkv,  g_qkv);
    cudaGetSymbolAddress((void**)&patt,  g_att);
    cudaGetSymbolAddress((void**)&ptmp,  g_tmp);
    cudaGetSymbolAddress((void**)&pmean, g_mean);

    // 1) x = transpose(features) + pos
    {
        dim3 grid(BNC, 3, 8), blk(32, 8);
        k_transpose<<<grid, blk>>>(feats, pos, px);
    }
    // 2) transformer layers
    for (int l = 0; l < NLAYERS; l++) {
        const float* qw = qkv_w  + (size_t)l * 256 * 768;
        const float* qb = qkv_b  + (size_t)l * 768;
        const float* pw = proj_w + (size_t)l * 256 * 256;
        const float* pb = proj_b + (size_t)l * 256;
        const float* lg = ln_g   + (size_t)l * 256;
        const float* lb = ln_b   + (size_t)l * 256;

        {   // qkv = x @ qw + qb
            dim3 grid(768 / 64, MTOT / 128);
            k_gemm_tf32<<<grid, 256>>>(px, qw, qb, nullptr, pqkv, 768);
        }
        {   // attention
            dim3 grid(BNC, NH);
            k_attn<<<grid, 256>>>(pqkv, patt);
        }
        {   // tmp = att @ pw + pb + x  (residual)
            dim3 grid(256 / 64, MTOT / 128);
            k_gemm_tf32<<<grid, 256>>>(patt, pw, pb, px, ptmp, 256);
        }
        // x = LN(tmp)
        k_ln<<<MTOT / 8, 256>>>(ptmp, lg, lb, px);
    }
    // 3) mean over sequence
    k_mean<<<BNC, 256>>>(px, pmean);
    // 4) classifier
    k_cls<<<BNC, 128>>>(pmean, cls_w1, cls_b1, cls_w2, cls_b2, out);
}